// round 1
// baseline (speedup 1.0000x reference)
#include <cuda_runtime.h>
#include <cuda_bf16.h>
#include <math.h>

#define S_LEN 2048
#define HID 1280
#define NH 16
#define HD 80
#define INTER 3420
#define NLAYER 8
#define WIN 64
#define MERGED 5120      // 4*HID
#define OUTDIM 3584
#define MTOK 512         // 2048/4

// ---------------- scratch (device globals; no allocation allowed) ----------------
__device__ float g_hs  [S_LEN * HID];
__device__ float g_x   [S_LEN * HID];
__device__ float g_qkv [S_LEN * 3 * HID];
__device__ float g_q   [NH * S_LEN * HD];
__device__ float g_k   [NH * S_LEN * HD];
__device__ float g_v   [NH * S_LEN * HD];
__device__ float g_att [S_LEN * HID];
__device__ float g_gate[S_LEN * INTER];
__device__ float g_up  [S_LEN * INTER];
__device__ float g_fc1 [MTOK * MERGED];

// ---------------- elementwise kernels ----------------
__global__ void copy_k(const float* __restrict__ src, float* __restrict__ dst, int n) {
    int i = blockIdx.x * blockDim.x + threadIdx.x;
    if (i < n) dst[i] = src[i];
}

__global__ void mul_k(float* __restrict__ a, const float* __restrict__ b, int n) {
    int i = blockIdx.x * blockDim.x + threadIdx.x;
    if (i < n) a[i] *= b[i];
}

// RMSNorm: one block per row of 1280
__global__ void __launch_bounds__(256) rmsnorm_k(const float* __restrict__ x,
                                                 const float* __restrict__ w,
                                                 float* __restrict__ y) {
    int row = blockIdx.x;
    const float* xr = x + (long)row * HID;
    float ss = 0.f;
    for (int i = threadIdx.x; i < HID; i += 256) { float v = xr[i]; ss += v * v; }
    // block reduce
    __shared__ float red[8];
    for (int o = 16; o > 0; o >>= 1) ss += __shfl_xor_sync(0xffffffffu, ss, o);
    if ((threadIdx.x & 31) == 0) red[threadIdx.x >> 5] = ss;
    __syncthreads();
    if (threadIdx.x < 32) {
        float v = (threadIdx.x < 8) ? red[threadIdx.x] : 0.f;
        for (int o = 4; o > 0; o >>= 1) v += __shfl_xor_sync(0xffffffffu, v, o);
        if (threadIdx.x == 0) red[0] = v;
    }
    __syncthreads();
    float inv = rsqrtf(red[0] / (float)HID + 1e-6f);
    for (int i = threadIdx.x; i < HID; i += 256)
        y[(long)row * HID + i] = xr[i] * inv * w[i];
}

// Split qkv [S, 3*HID] -> q,k,v [H,S,D] with RoPE on q,k
__global__ void rope_split_k(const float* __restrict__ qkv,
                             const float* __restrict__ cs,
                             const float* __restrict__ sn,
                             float* __restrict__ gq, float* __restrict__ gk,
                             float* __restrict__ gv) {
    int idx = blockIdx.x * blockDim.x + threadIdx.x;
    if (idx >= S_LEN * HID) return;
    int d = idx % HD;
    int h = (idx / HD) % NH;
    int s = idx / HID;
    const float* base = qkv + (long)s * (3 * HID);
    float c = cs[s * HD + d];
    float si = sn[s * HD + d];
    int f = h * HD + d;
    float qv = base[f];
    float kv = base[HID + f];
    float vv = base[2 * HID + f];
    int dr = (d < HD / 2) ? (d + HD / 2) : (d - HD / 2);
    float sgn = (d < HD / 2) ? -1.f : 1.f;
    float qr = sgn * base[h * HD + dr];
    float kr = sgn * base[HID + h * HD + dr];
    long o = ((long)h * S_LEN + s) * HD + d;
    gq[o] = qv * c + qr * si;
    gk[o] = kv * c + kr * si;
    gv[o] = vv;
}

// ---------------- flash attention (full or 64-window) ----------------
// grid: (S/64, H), block 256. Each thread: query qi = tid/4, D-slice of 20.
__global__ void __launch_bounds__(256) attn_k(const float* __restrict__ Q,
                                              const float* __restrict__ K,
                                              const float* __restrict__ V,
                                              const float* __restrict__ mask,
                                              int windowed,
                                              float* __restrict__ O) {
    __shared__ float Ks[64][HD];
    __shared__ float Vs[64][HD];
    int h = blockIdx.y;
    int q0 = blockIdx.x * 64;
    int tid = threadIdx.x;
    int qi = tid >> 2;
    int part = tid & 3;
    int d0 = part * 20;
    int q = q0 + qi;

    const float* Qb = Q + ((long)h * S_LEN + q) * HD;
    float qr[20];
#pragma unroll
    for (int i = 0; i < 20; ++i) qr[i] = Qb[d0 + i];

    float m = -3.0e38f, l = 0.f;
    float oacc[20];
#pragma unroll
    for (int i = 0; i < 20; ++i) oacc[i] = 0.f;

    int kvs = windowed ? q0 : 0;
    int kve = windowed ? q0 + 64 : S_LEN;
    const float scale = 0.11180339887498949f; // 1/sqrt(80)
    const float NEG = -3.0e38f;

    for (int kv0 = kvs; kv0 < kve; kv0 += 64) {
        __syncthreads();
        const float* Kb = K + ((long)h * S_LEN + kv0) * HD;
        const float* Vb = V + ((long)h * S_LEN + kv0) * HD;
        for (int i = tid; i < 64 * HD; i += 256) {
            Ks[i / HD][i % HD] = Kb[i];
            Vs[i / HD][i % HD] = Vb[i];
        }
        __syncthreads();
#pragma unroll 1
        for (int jc = 0; jc < 4; ++jc) {
            float sc[16];
#pragma unroll
            for (int jj = 0; jj < 16; ++jj) {
                int j = jc * 16 + jj;
                float a = 0.f;
#pragma unroll
                for (int dd = 0; dd < 20; ++dd) a += qr[dd] * Ks[j][d0 + dd];
                a += __shfl_xor_sync(0xffffffffu, a, 1);
                a += __shfl_xor_sync(0xffffffffu, a, 2);
                float mv;
                if (windowed)
                    mv = mask[(((long)(q0 >> 6) * 64 + qi) * 64) + j];
                else
                    mv = mask[(long)q * S_LEN + (kv0 + j)];
                sc[jj] = a * scale + (1.f - mv) * NEG;
            }
            float tmax = sc[0];
#pragma unroll
            for (int jj = 1; jj < 16; ++jj) tmax = fmaxf(tmax, sc[jj]);
            float mn = fmaxf(m, tmax);
            float corr = expf(m - mn);
#pragma unroll
            for (int dd = 0; dd < 20; ++dd) oacc[dd] *= corr;
            float ls = 0.f;
#pragma unroll
            for (int jj = 0; jj < 16; ++jj) {
                int j = jc * 16 + jj;
                float p = expf(sc[jj] - mn);
                ls += p;
#pragma unroll
                for (int dd = 0; dd < 20; ++dd) oacc[dd] += p * Vs[j][d0 + dd];
            }
            l = l * corr + ls;
            m = mn;
        }
    }
    float invl = 1.f / l;
#pragma unroll
    for (int dd = 0; dd < 20; ++dd)
        O[(long)q * HID + h * HD + d0 + dd] = oacc[dd] * invl;
}

// ---------------- SGEMM: C[M,N] = act(A[M,K] @ B[K,N] + bias) (+ resid) ----------------
// BM=BN=128, BK=16, 256 threads, 8x8 per thread. M must be multiple of 128.
#define GBM 128
#define GBN 128
#define GBK 16

template <int ACT, bool RES>
__global__ void __launch_bounds__(256) sgemm_k(const float* __restrict__ A,
                                               const float* __restrict__ B,
                                               const float* __restrict__ bias,
                                               const float* __restrict__ resid,
                                               float* __restrict__ C,
                                               int M, int N, int K) {
    __shared__ float As[GBK][GBM];
    __shared__ float Bs[GBK][GBN];
    int bm = blockIdx.y, bn = blockIdx.x;
    int tid = threadIdx.x;
    int tm = (tid / 16) * 8;
    int tn = (tid % 16) * 8;
    float acc[8][8];
#pragma unroll
    for (int i = 0; i < 8; ++i)
#pragma unroll
        for (int j = 0; j < 8; ++j) acc[i][j] = 0.f;

    int ar = tid >> 2;          // 0..63
    int ac4 = (tid & 3) * 4;    // 0,4,8,12
    int br = tid >> 5;          // 0..7
    int bc4 = (tid & 31) * 4;   // 0..124
    const float* Ab = A + (long)(bm * GBM) * K;
    int gcol4 = bn * GBN + bc4;

    for (int k0 = 0; k0 < K; k0 += GBK) {
#pragma unroll
        for (int rr = 0; rr < 2; ++rr) {
            int row = ar + rr * 64;
            float4 v = make_float4(0.f, 0.f, 0.f, 0.f);
            if (k0 + ac4 < K) v = *(const float4*)(Ab + (long)row * K + k0 + ac4);
            As[ac4 + 0][row] = v.x;
            As[ac4 + 1][row] = v.y;
            As[ac4 + 2][row] = v.z;
            As[ac4 + 3][row] = v.w;
        }
#pragma unroll
        for (int rr = 0; rr < 2; ++rr) {
            int krow = br + rr * 8;
            float4 v = make_float4(0.f, 0.f, 0.f, 0.f);
            int gk = k0 + krow;
            if (gk < K && gcol4 < N) v = *(const float4*)(B + (long)gk * N + gcol4);
            *(float4*)&Bs[krow][bc4] = v;
        }
        __syncthreads();
#pragma unroll
        for (int kk = 0; kk < GBK; ++kk) {
            float ra[8], rb[8];
#pragma unroll
            for (int i = 0; i < 8; ++i) ra[i] = As[kk][tm + i];
#pragma unroll
            for (int j = 0; j < 8; ++j) rb[j] = Bs[kk][tn + j];
#pragma unroll
            for (int i = 0; i < 8; ++i)
#pragma unroll
                for (int j = 0; j < 8; ++j) acc[i][j] += ra[i] * rb[j];
        }
        __syncthreads();
    }
#pragma unroll
    for (int i = 0; i < 8; ++i) {
        int row = bm * GBM + tm + i;
#pragma unroll
        for (int j = 0; j < 8; ++j) {
            int col = bn * GBN + tn + j;
            if (col < N) {
                float v = acc[i][j] + bias[col];
                if (ACT == 1) v = v / (1.f + expf(-v));                       // SiLU
                if (ACT == 2) v = 0.5f * v * (1.f + erff(v * 0.70710678118654752f)); // exact GELU
                if (RES) v += resid[(long)row * N + col];
                C[(long)row * N + col] = v;
            }
        }
    }
}

// ---------------- host ----------------
static inline dim3 gemm_grid(int M, int N) { return dim3((N + GBN - 1) / GBN, M / GBM); }

extern "C" void kernel_launch(void* const* d_in, const int* in_sizes, int n_in,
                              void* d_out, int out_size) {
    const float* in_hs   = (const float*)d_in[0];
    const float* fmask   = (const float*)d_in[1];
    const float* wmask   = (const float*)d_in[2];
    const float* cosd    = (const float*)d_in[3];
    const float* sind    = (const float*)d_in[4];
    const float* norm1_w = (const float*)d_in[5];
    const float* norm2_w = (const float*)d_in[6];
    const float* qkv_w   = (const float*)d_in[7];
    const float* qkv_b   = (const float*)d_in[8];
    const float* proj_w  = (const float*)d_in[9];
    const float* proj_b  = (const float*)d_in[10];
    const float* gate_w  = (const float*)d_in[11];
    const float* gate_b  = (const float*)d_in[12];
    const float* up_w    = (const float*)d_in[13];
    const float* up_b    = (const float*)d_in[14];
    const float* down_w  = (const float*)d_in[15];
    const float* down_b  = (const float*)d_in[16];
    const float* ln_q_w  = (const float*)d_in[17];
    const float* fc1_w   = (const float*)d_in[18];
    const float* fc1_b   = (const float*)d_in[19];
    const float* fc2_w   = (const float*)d_in[20];
    const float* fc2_b   = (const float*)d_in[21];
    float* out = (float*)d_out;

    float *hs, *x, *qkv, *q, *k, *v, *att, *gate, *up, *fc1;
    cudaGetSymbolAddress((void**)&hs, g_hs);
    cudaGetSymbolAddress((void**)&x, g_x);
    cudaGetSymbolAddress((void**)&qkv, g_qkv);
    cudaGetSymbolAddress((void**)&q, g_q);
    cudaGetSymbolAddress((void**)&k, g_k);
    cudaGetSymbolAddress((void**)&v, g_v);
    cudaGetSymbolAddress((void**)&att, g_att);
    cudaGetSymbolAddress((void**)&gate, g_gate);
    cudaGetSymbolAddress((void**)&up, g_up);
    cudaGetSymbolAddress((void**)&fc1, g_fc1);

    const int nhid = S_LEN * HID;
    copy_k<<<(nhid + 255) / 256, 256>>>(in_hs, hs, nhid);

    for (int i = 0; i < NLAYER; ++i) {
        int full = (i == 3 || i == 7) ? 1 : 0;
        // x = rmsnorm(hs, norm1_w[i])
        rmsnorm_k<<<S_LEN, 256>>>(hs, norm1_w + (long)i * HID, x);
        // qkv = x @ qkv_w[i] + qkv_b[i]
        sgemm_k<0, false><<<gemm_grid(S_LEN, 3 * HID), 256>>>(
            x, qkv_w + (long)i * HID * 3 * HID, qkv_b + (long)i * 3 * HID,
            nullptr, qkv, S_LEN, 3 * HID, HID);
        // split + rope
        rope_split_k<<<(nhid + 255) / 256, 256>>>(qkv, cosd, sind, q, k, v);
        // attention
        attn_k<<<dim3(S_LEN / 64, NH), 256>>>(q, k, v, full ? fmask : wmask,
                                              full ? 0 : 1, att);
        // hs = hs + att @ proj_w[i] + proj_b[i]
        sgemm_k<0, true><<<gemm_grid(S_LEN, HID), 256>>>(
            att, proj_w + (long)i * HID * HID, proj_b + (long)i * HID,
            hs, hs, S_LEN, HID, HID);
        // x = rmsnorm(hs, norm2_w[i])
        rmsnorm_k<<<S_LEN, 256>>>(hs, norm2_w + (long)i * HID, x);
        // gate = silu(x @ gate_w + gate_b); up = x @ up_w + up_b
        sgemm_k<1, false><<<gemm_grid(S_LEN, INTER), 256>>>(
            x, gate_w + (long)i * HID * INTER, gate_b + (long)i * INTER,
            nullptr, gate, S_LEN, INTER, HID);
        sgemm_k<0, false><<<gemm_grid(S_LEN, INTER), 256>>>(
            x, up_w + (long)i * HID * INTER, up_b + (long)i * INTER,
            nullptr, up, S_LEN, INTER, HID);
        // gate *= up
        {
            int n = S_LEN * INTER;
            mul_k<<<(n + 255) / 256, 256>>>(gate, up, n);
        }
        // hs = hs + gate @ down_w + down_b
        sgemm_k<0, true><<<gemm_grid(S_LEN, HID), 256>>>(
            gate, down_w + (long)i * INTER * HID, down_b + (long)i * HID,
            hs, hs, S_LEN, HID, INTER);
    }

    // patch merger
    rmsnorm_k<<<S_LEN, 256>>>(hs, ln_q_w, x);  // x viewed as [512, 5120]
    sgemm_k<2, false><<<gemm_grid(MTOK, MERGED), 256>>>(
        x, fc1_w, fc1_b, nullptr, fc1, MTOK, MERGED, MERGED);
    sgemm_k<0, false><<<gemm_grid(MTOK, OUTDIM), 256>>>(
        fc1, fc2_w, fc2_b, nullptr, out, MTOK, OUTDIM, MERGED);
}

// round 3
// speedup vs baseline: 1.2771x; 1.2771x over previous
#include <cuda_runtime.h>
#include <cuda_bf16.h>
#include <math.h>
#include <stdint.h>

#define S_LEN 2048
#define HID 1280
#define NH 16
#define HD 80
#define INTER 3420
#define NLAYER 8
#define WIN 64
#define MERGED 5120      // 4*HID
#define OUTDIM 3584
#define MTOK 512         // 2048/4

// ---------------- scratch (device globals; no allocation allowed) ----------------
__device__ float g_hs  [S_LEN * HID];
__device__ float g_x   [S_LEN * HID];
__device__ float g_qkv [S_LEN * 3 * HID];
__device__ float g_q   [NH * S_LEN * HD];
__device__ float g_k   [NH * S_LEN * HD];
__device__ float g_v   [NH * S_LEN * HD];
__device__ float g_att [S_LEN * HID];
__device__ float g_gate[S_LEN * INTER];
__device__ float g_fc1 [MTOK * MERGED];

// ---------------- elementwise kernels ----------------
__global__ void copy_k(const float* __restrict__ src, float* __restrict__ dst, int n) {
    int i = blockIdx.x * blockDim.x + threadIdx.x;
    if (i < n) dst[i] = src[i];
}

// RMSNorm: one block per row of 1280
__global__ void __launch_bounds__(256) rmsnorm_k(const float* __restrict__ x,
                                                 const float* __restrict__ w,
                                                 float* __restrict__ y) {
    int row = blockIdx.x;
    const float* xr = x + (long)row * HID;
    float ss = 0.f;
    for (int i = threadIdx.x; i < HID; i += 256) { float v = xr[i]; ss += v * v; }
    __shared__ float red[8];
    for (int o = 16; o > 0; o >>= 1) ss += __shfl_xor_sync(0xffffffffu, ss, o);
    if ((threadIdx.x & 31) == 0) red[threadIdx.x >> 5] = ss;
    __syncthreads();
    if (threadIdx.x < 32) {
        float v = (threadIdx.x < 8) ? red[threadIdx.x] : 0.f;
        for (int o = 4; o > 0; o >>= 1) v += __shfl_xor_sync(0xffffffffu, v, o);
        if (threadIdx.x == 0) red[0] = v;
    }
    __syncthreads();
    float inv = rsqrtf(red[0] / (float)HID + 1e-6f);
    for (int i = threadIdx.x; i < HID; i += 256)
        y[(long)row * HID + i] = xr[i] * inv * w[i];
}

// Split qkv [S, 3*HID] -> q,k,v [H,S,D] with RoPE on q,k
__global__ void rope_split_k(const float* __restrict__ qkv,
                             const float* __restrict__ cs,
                             const float* __restrict__ sn,
                             float* __restrict__ gq, float* __restrict__ gk,
                             float* __restrict__ gv) {
    int idx = blockIdx.x * blockDim.x + threadIdx.x;
    if (idx >= S_LEN * HID) return;
    int d = idx % HD;
    int h = (idx / HD) % NH;
    int s = idx / HID;
    const float* base = qkv + (long)s * (3 * HID);
    float c = cs[s * HD + d];
    float si = sn[s * HD + d];
    int f = h * HD + d;
    float qv = base[f];
    float kv = base[HID + f];
    float vv = base[2 * HID + f];
    int dr = (d < HD / 2) ? (d + HD / 2) : (d - HD / 2);
    float sgn = (d < HD / 2) ? -1.f : 1.f;
    float qr = sgn * base[h * HD + dr];
    float kr = sgn * base[HID + h * HD + dr];
    long o = ((long)h * S_LEN + s) * HD + d;
    gq[o] = qv * c + qr * si;
    gk[o] = kv * c + kr * si;
    gv[o] = vv;
}

// ---------------- flash attention (full or 64-window) ----------------
__global__ void __launch_bounds__(256) attn_k(const float* __restrict__ Q,
                                              const float* __restrict__ K,
                                              const float* __restrict__ V,
                                              const float* __restrict__ mask,
                                              int windowed,
                                              float* __restrict__ O) {
    __shared__ float Ks[64][HD];
    __shared__ float Vs[64][HD];
    int h = blockIdx.y;
    int q0 = blockIdx.x * 64;
    int tid = threadIdx.x;
    int qi = tid >> 2;
    int part = tid & 3;
    int d0 = part * 20;
    int q = q0 + qi;

    const float* Qb = Q + ((long)h * S_LEN + q) * HD;
    float qr[20];
#pragma unroll
    for (int i = 0; i < 20; ++i) qr[i] = Qb[d0 + i];

    float m = -3.0e38f, l = 0.f;
    float oacc[20];
#pragma unroll
    for (int i = 0; i < 20; ++i) oacc[i] = 0.f;

    int kvs = windowed ? q0 : 0;
    int kve = windowed ? q0 + 64 : S_LEN;
    const float scale = 0.11180339887498949f; // 1/sqrt(80)
    const float NEG = -3.0e38f;

    for (int kv0 = kvs; kv0 < kve; kv0 += 64) {
        __syncthreads();
        const float* Kb = K + ((long)h * S_LEN + kv0) * HD;
        const float* Vb = V + ((long)h * S_LEN + kv0) * HD;
        for (int i = tid; i < 64 * HD; i += 256) {
            Ks[i / HD][i % HD] = Kb[i];
            Vs[i / HD][i % HD] = Vb[i];
        }
        __syncthreads();
#pragma unroll 1
        for (int jc = 0; jc < 4; ++jc) {
            float sc[16];
#pragma unroll
            for (int jj = 0; jj < 16; ++jj) {
                int j = jc * 16 + jj;
                float a = 0.f;
#pragma unroll
                for (int dd = 0; dd < 20; ++dd) a += qr[dd] * Ks[j][d0 + dd];
                a += __shfl_xor_sync(0xffffffffu, a, 1);
                a += __shfl_xor_sync(0xffffffffu, a, 2);
                float mv;
                if (windowed)
                    mv = mask[(((long)(q0 >> 6) * 64 + qi) * 64) + j];
                else
                    mv = mask[(long)q * S_LEN + (kv0 + j)];
                sc[jj] = a * scale + (1.f - mv) * NEG;
            }
            float tmax = sc[0];
#pragma unroll
            for (int jj = 1; jj < 16; ++jj) tmax = fmaxf(tmax, sc[jj]);
            float mn = fmaxf(m, tmax);
            float corr = expf(m - mn);
#pragma unroll
            for (int dd = 0; dd < 20; ++dd) oacc[dd] *= corr;
            float ls = 0.f;
#pragma unroll
            for (int jj = 0; jj < 16; ++jj) {
                int j = jc * 16 + jj;
                float p = expf(sc[jj] - mn);
                ls += p;
#pragma unroll
                for (int dd = 0; dd < 20; ++dd) oacc[dd] += p * Vs[j][d0 + dd];
            }
            l = l * corr + ls;
            m = mn;
        }
    }
    float invl = 1.f / l;
#pragma unroll
    for (int dd = 0; dd < 20; ++dd)
        O[(long)q * HID + h * HD + d0 + dd] = oacc[dd] * invl;
}

// ---------------- 3xTF32 tensor-core GEMM ----------------
// C[M,N] = epi(A[M,K] @ B[K,N] + bias)   (EPI: 0 none, 1 SiLU, 2 GELU,
//                                          3 += res, 4 *= res)
// BM=BN=128, BK=16, 256 threads (8 warps, 2x4), warp tile 64x32,
// mma.m16n8k8.tf32 tiles 4x4 per warp. Each input split big+small tf32;
// acc += Ab*Bb + Ab*Bs + As*Bb (error ~2^-22).
#define GBM 128
#define GBN 128
#define GBK 16
#define SPAD 8
#define SSTR (GBM + SPAD)   // 136 floats -> bank stride 8

__device__ __forceinline__ float tf32_big(float x) {
    uint32_t r;
    asm("cvt.rna.tf32.f32 %0, %1;" : "=r"(r) : "f"(x));
    return __uint_as_float(r);
}

__device__ __forceinline__ void mma_tf32(float c[4], const uint32_t a[4], const uint32_t b[2]) {
    asm volatile(
        "mma.sync.aligned.m16n8k8.row.col.f32.tf32.tf32.f32 "
        "{%0,%1,%2,%3}, {%4,%5,%6,%7}, {%8,%9}, {%0,%1,%2,%3};"
        : "+f"(c[0]), "+f"(c[1]), "+f"(c[2]), "+f"(c[3])
        : "r"(a[0]), "r"(a[1]), "r"(a[2]), "r"(a[3]), "r"(b[0]), "r"(b[1]));
}

template <int EPI>
__global__ void __launch_bounds__(256, 2) mmagemm_k(const float* __restrict__ A,
                                                    const float* __restrict__ B,
                                                    const float* __restrict__ bias,
                                                    const float* __restrict__ res,
                                                    float* __restrict__ C,
                                                    int M, int N, int K) {
    __shared__ float AsB[GBK][SSTR];
    __shared__ float AsS[GBK][SSTR];
    __shared__ float BsB[GBK][SSTR];
    __shared__ float BsS[GBK][SSTR];

    int tid = threadIdx.x;
    int lane = tid & 31;
    int warp = tid >> 5;
    int warpM = warp & 1;     // 0..1  -> 64-row half
    int warpN = warp >> 1;    // 0..3  -> 32-col quarter
    int g = lane >> 2;        // 0..7
    int tg = lane & 3;        // 0..3

    int bmBase = blockIdx.y * GBM;
    int bnBase = blockIdx.x * GBN;

    float acc[4][4][4];
#pragma unroll
    for (int mi = 0; mi < 4; ++mi)
#pragma unroll
        for (int ni = 0; ni < 4; ++ni)
#pragma unroll
            for (int r = 0; r < 4; ++r) acc[mi][ni][r] = 0.f;

    // A load: 128 rows x 16 k; thread -> row = tid&127, k-half = (tid>>7)*8
    int arow = tid & 127;
    int ahalf = (tid >> 7) * 8;
    const float* Ab = A + (long)(bmBase + arow) * K;
    // B load: 16 k-rows x 128 cols; thread -> k = tid>>4, col4 = (tid&15)*4 (+64)
    int bk = tid >> 4;
    int bn = (tid & 15) * 4;

    for (int k0 = 0; k0 < K; k0 += GBK) {
        // --- A tile (big/small split) ---
#pragma unroll
        for (int h4 = 0; h4 < 2; ++h4) {
            int kc = ahalf + h4 * 4;
            float4 v = make_float4(0.f, 0.f, 0.f, 0.f);
            if (k0 + kc < K) v = *(const float4*)(Ab + k0 + kc);
            float bx = tf32_big(v.x), by = tf32_big(v.y), bz = tf32_big(v.z), bw = tf32_big(v.w);
            AsB[kc + 0][arow] = bx;
            AsB[kc + 1][arow] = by;
            AsB[kc + 2][arow] = bz;
            AsB[kc + 3][arow] = bw;
            AsS[kc + 0][arow] = tf32_big(v.x - bx);
            AsS[kc + 1][arow] = tf32_big(v.y - by);
            AsS[kc + 2][arow] = tf32_big(v.z - bz);
            AsS[kc + 3][arow] = tf32_big(v.w - bw);
        }
        // --- B tile (big/small split) ---
#pragma unroll
        for (int h4 = 0; h4 < 2; ++h4) {
            int nc = bn + h4 * 64;
            int gcol = bnBase + nc;
            float4 v = make_float4(0.f, 0.f, 0.f, 0.f);
            if (k0 + bk < K && gcol < N) v = *(const float4*)(B + (long)(k0 + bk) * N + gcol);
            float4 wb, ws;
            wb.x = tf32_big(v.x); ws.x = tf32_big(v.x - wb.x);
            wb.y = tf32_big(v.y); ws.y = tf32_big(v.y - wb.y);
            wb.z = tf32_big(v.z); ws.z = tf32_big(v.z - wb.z);
            wb.w = tf32_big(v.w); ws.w = tf32_big(v.w - wb.w);
            *(float4*)&BsB[bk][nc] = wb;
            *(float4*)&BsS[bk][nc] = ws;
        }
        __syncthreads();

#pragma unroll
        for (int ks = 0; ks < GBK; ks += 8) {
            // Fragment layout (m16n8k8.tf32):
            // a0=(g, tg) a1=(g+8, tg) a2=(g, tg+4) a3=(g+8, tg+4)
            // b0=(tg, g) b1=(tg+4, g)
            uint32_t aB[4][4], aS[4][4];
            uint32_t bB[4][2], bS[4][2];
#pragma unroll
            for (int mi = 0; mi < 4; ++mi) {
                int m = warpM * 64 + mi * 16 + g;
                aB[mi][0] = __float_as_uint(AsB[ks + tg][m]);
                aB[mi][1] = __float_as_uint(AsB[ks + tg][m + 8]);
                aB[mi][2] = __float_as_uint(AsB[ks + tg + 4][m]);
                aB[mi][3] = __float_as_uint(AsB[ks + tg + 4][m + 8]);
                aS[mi][0] = __float_as_uint(AsS[ks + tg][m]);
                aS[mi][1] = __float_as_uint(AsS[ks + tg][m + 8]);
                aS[mi][2] = __float_as_uint(AsS[ks + tg + 4][m]);
                aS[mi][3] = __float_as_uint(AsS[ks + tg + 4][m + 8]);
            }
#pragma unroll
            for (int ni = 0; ni < 4; ++ni) {
                int n = warpN * 32 + ni * 8 + g;
                bB[ni][0] = __float_as_uint(BsB[ks + tg][n]);
                bB[ni][1] = __float_as_uint(BsB[ks + tg + 4][n]);
                bS[ni][0] = __float_as_uint(BsS[ks + tg][n]);
                bS[ni][1] = __float_as_uint(BsS[ks + tg + 4][n]);
            }
#pragma unroll
            for (int mi = 0; mi < 4; ++mi)
#pragma unroll
                for (int ni = 0; ni < 4; ++ni) {
                    mma_tf32(acc[mi][ni], aB[mi], bB[ni]);
                    mma_tf32(acc[mi][ni], aB[mi], bS[ni]);
                    mma_tf32(acc[mi][ni], aS[mi], bB[ni]);
                }
        }
        __syncthreads();
    }

    // ---- epilogue ----
    // c0=(g, 2tg) c1=(g, 2tg+1) c2=(g+8, 2tg) c3=(g+8, 2tg+1)
#pragma unroll
    for (int mi = 0; mi < 4; ++mi) {
        int row0 = bmBase + warpM * 64 + mi * 16 + g;
#pragma unroll
        for (int ni = 0; ni < 4; ++ni) {
            int col = bnBase + warpN * 32 + ni * 8 + 2 * tg;
            if (col >= N) continue;
            float b0 = bias[col], b1 = bias[col + 1];
#pragma unroll
            for (int rh = 0; rh < 2; ++rh) {
                int row = row0 + rh * 8;
                float v0 = acc[mi][ni][rh * 2 + 0] + b0;
                float v1 = acc[mi][ni][rh * 2 + 1] + b1;
                if (EPI == 1) {
                    v0 = v0 / (1.f + expf(-v0));
                    v1 = v1 / (1.f + expf(-v1));
                } else if (EPI == 2) {
                    v0 = 0.5f * v0 * (1.f + erff(v0 * 0.70710678118654752f));
                    v1 = 0.5f * v1 * (1.f + erff(v1 * 0.70710678118654752f));
                } else if (EPI == 3) {
                    v0 += res[(long)row * N + col];
                    v1 += res[(long)row * N + col + 1];
                } else if (EPI == 4) {
                    v0 *= res[(long)row * N + col];
                    v1 *= res[(long)row * N + col + 1];
                }
                C[(long)row * N + col] = v0;
                C[(long)row * N + col + 1] = v1;
            }
        }
    }
}

// ---------------- host ----------------
static inline dim3 gemm_grid(int M, int N) { return dim3((N + GBN - 1) / GBN, M / GBM); }

extern "C" void kernel_launch(void* const* d_in, const int* in_sizes, int n_in,
                              void* d_out, int out_size) {
    const float* in_hs   = (const float*)d_in[0];
    const float* fmask   = (const float*)d_in[1];
    const float* wmask   = (const float*)d_in[2];
    const float* cosd    = (const float*)d_in[3];
    const float* sind    = (const float*)d_in[4];
    const float* norm1_w = (const float*)d_in[5];
    const float* norm2_w = (const float*)d_in[6];
    const float* qkv_w   = (const float*)d_in[7];
    const float* qkv_b   = (const float*)d_in[8];
    const float* proj_w  = (const float*)d_in[9];
    const float* proj_b  = (const float*)d_in[10];
    const float* gate_w  = (const float*)d_in[11];
    const float* gate_b  = (const float*)d_in[12];
    const float* up_w    = (const float*)d_in[13];
    const float* up_b    = (const float*)d_in[14];
    const float* down_w  = (const float*)d_in[15];
    const float* down_b  = (const float*)d_in[16];
    const float* ln_q_w  = (const float*)d_in[17];
    const float* fc1_w   = (const float*)d_in[18];
    const float* fc1_b   = (const float*)d_in[19];
    const float* fc2_w   = (const float*)d_in[20];
    const float* fc2_b   = (const float*)d_in[21];
    float* out = (float*)d_out;

    float *hs, *x, *qkv, *q, *k, *v, *att, *gate, *fc1;
    cudaGetSymbolAddress((void**)&hs, g_hs);
    cudaGetSymbolAddress((void**)&x, g_x);
    cudaGetSymbolAddress((void**)&qkv, g_qkv);
    cudaGetSymbolAddress((void**)&q, g_q);
    cudaGetSymbolAddress((void**)&k, g_k);
    cudaGetSymbolAddress((void**)&v, g_v);
    cudaGetSymbolAddress((void**)&att, g_att);
    cudaGetSymbolAddress((void**)&gate, g_gate);
    cudaGetSymbolAddress((void**)&fc1, g_fc1);

    const int nhid = S_LEN * HID;
    copy_k<<<(nhid + 255) / 256, 256>>>(in_hs, hs, nhid);

    for (int i = 0; i < NLAYER; ++i) {
        int full = (i == 3 || i == 7) ? 1 : 0;
        rmsnorm_k<<<S_LEN, 256>>>(hs, norm1_w + (long)i * HID, x);
        mmagemm_k<0><<<gemm_grid(S_LEN, 3 * HID), 256>>>(
            x, qkv_w + (long)i * HID * 3 * HID, qkv_b + (long)i * 3 * HID,
            nullptr, qkv, S_LEN, 3 * HID, HID);
        rope_split_k<<<(nhid + 255) / 256, 256>>>(qkv, cosd, sind, q, k, v);
        attn_k<<<dim3(S_LEN / 64, NH), 256>>>(q, k, v, full ? fmask : wmask,
                                              full ? 0 : 1, att);
        mmagemm_k<3><<<gemm_grid(S_LEN, HID), 256>>>(
            att, proj_w + (long)i * HID * HID, proj_b + (long)i * HID,
            hs, hs, S_LEN, HID, HID);
        rmsnorm_k<<<S_LEN, 256>>>(hs, norm2_w + (long)i * HID, x);
        mmagemm_k<1><<<gemm_grid(S_LEN, INTER), 256>>>(
            x, gate_w + (long)i * HID * INTER, gate_b + (long)i * INTER,
            nullptr, gate, S_LEN, INTER, HID);
        mmagemm_k<4><<<gemm_grid(S_LEN, INTER), 256>>>(
            x, up_w + (long)i * HID * INTER, up_b + (long)i * INTER,
            gate, gate, S_LEN, INTER, HID);
        mmagemm_k<3><<<gemm_grid(S_LEN, HID), 256>>>(
            gate, down_w + (long)i * INTER * HID, down_b + (long)i * HID,
            hs, hs, S_LEN, HID, INTER);
    }

    // patch merger
    rmsnorm_k<<<S_LEN, 256>>>(hs, ln_q_w, x);  // x viewed as [512, 5120]
    mmagemm_k<2><<<gemm_grid(MTOK, MERGED), 256>>>(
        x, fc1_w, fc1_b, nullptr, fc1, MTOK, MERGED, MERGED);
    mmagemm_k<0><<<gemm_grid(MTOK, OUTDIM), 256>>>(
        fc1, fc2_w, fc2_b, nullptr, out, MTOK, OUTDIM, MERGED);
}